// round 8
// baseline (speedup 1.0000x reference)
#include <cuda_runtime.h>
#include <cstdint>

#define FEAT      256
#define PRE_CAP   16384
#define JT        8
#define CHUNK_MAX 2048          // ceil(PRE_CAP / JT)
#define DEF_INSERT 999000
#define HB        1184          // hash blocks: 8 CTAs/SM * 148 SMs
#define HT        (HB * 256)

typedef unsigned long long u64;

// ---------------- device scratch (no allocations allowed; zero-init) ----------------
__device__ u64      g_pre[PRE_CAP];     // ((0x7FFFFF - r) << 32) | index
__device__ int      g_npre;             // reset in k_gather each run
__device__ int      g_rank[PRE_CAP];    // atomic partial ranks; self-cleaned in finalize
__device__ uint32_t g_topidx[PRE_CAP];  // ordered sampled indices
__device__ unsigned g_done;             // rank-kernel ticket; self-cleaned

// ---------------- Threefry-2x32, 20 rounds, partitionable layout (JAX-exact) ----------------
__device__ __forceinline__ uint32_t rotl32(uint32_t x, int d) {
    return __funnelshift_l(x, x, d);
}

__device__ __forceinline__ uint32_t jax_bits32(uint32_t j) {
    const uint32_t k0 = 0u, k1 = 42u;
    const uint32_t ks2 = k0 ^ k1 ^ 0x1BD11BDAu;
    uint32_t x0 = 0u + k0, x1 = j + k1;
#define TF_R(r) { x0 += x1; x1 = rotl32(x1, (r)); x1 ^= x0; }
    TF_R(13) TF_R(15) TF_R(26) TF_R(6)   x0 += k1;  x1 += ks2 + 1u;
    TF_R(17) TF_R(29) TF_R(16) TF_R(24)  x0 += ks2; x1 += k0  + 2u;
    TF_R(13) TF_R(15) TF_R(26) TF_R(6)   x0 += k0;  x1 += k1  + 3u;
    TF_R(17) TF_R(29) TF_R(16) TF_R(24)  x0 += k1;  x1 += ks2 + 4u;
    TF_R(13) TF_R(15) TF_R(26) TF_R(6)   x0 += ks2; x1 += k0  + 5u;
#undef TF_R
    return x0 ^ x1;   // XOR-fold (jax_threefry_partitionable)
}

__device__ __forceinline__ int read_scalar(const int* p, int defv) {
    return p ? p[0] : defv;
}

__device__ __forceinline__ void warp_push(bool push, uint32_t r, int j, int lane) {
    unsigned mask = __ballot_sync(0xFFFFFFFFu, push);
    if (mask) {
        int leader = __ffs(mask) - 1;
        int base = 0;
        if (lane == leader) base = atomicAdd(&g_npre, __popc(mask));
        base = __shfl_sync(0xFFFFFFFFu, base, leader);
        if (push) {
            int pos = base + __popc(mask & ((1u << lane) - 1u));
            if (pos < PRE_CAP)
                g_pre[pos] = ((u64)(0x7FFFFFu - r) << 32) | (uint32_t)j;
        }
    }
}

// ---------------- K1: hash all slots (2-way ILP), push top-region survivors ----------------
__global__ void __launch_bounds__(256, 8)
k_hash_push(const int* __restrict__ d_size, int max_size, int data_len, int nsamp) {
    int new_size = read_scalar(d_size, max_size) + data_len;
    if (new_size > max_size) new_size = max_size;
    if (new_size < 0) new_size = 0;

    // keep top `keep` mantissa values so expected survivors ~= 1.25 * nsamp
    uint32_t precut = 0u;
    if (new_size > 0) {
        u64 keep = ((u64)nsamp * 5u / 4u) << 23;
        keep /= (u64)new_size;
        precut = (keep >= 0x800000ull) ? 0u : (uint32_t)(0x800000ull - keep);
    }

    const int lane = threadIdx.x & 31;
    const int gtid = blockIdx.x * 256 + threadIdx.x;

    for (int j = gtid; j - lane < max_size; j += 2 * HT) {
        int j2 = j + HT;
        // two independent threefry chains -> 2x ILP on the ALU dep chain
        uint32_t rA = 0u, rB = 0u;
        bool pA = false, pB = false;
        if (j  < new_size) { rA = jax_bits32((uint32_t)j)  >> 9; pA = (rA >= precut); }
        if (j2 < new_size) { rB = jax_bits32((uint32_t)j2) >> 9; pB = (rB >= precut); }
        warp_push(pA, rA, j,  lane);
        warp_push(pB, rB, j2, lane);
    }
}

// ---------------- K2: tiled exact rank + last-block finalize ----------------
__global__ void k_rank(int nsamp) {
    __shared__ u64 sk[CHUNK_MAX];
    __shared__ bool amlast;

    int npre = g_npre;
    if (npre > PRE_CAP) npre = PRE_CAP;
    int chunk = (npre + JT - 1) / JT;

    int t = blockIdx.x * blockDim.x + threadIdx.x;
    int j0 = blockIdx.y * chunk;
    int j1 = j0 + chunk; if (j1 > npre) j1 = npre;

    if ((int)(blockIdx.x * blockDim.x) < npre && j0 < npre) {
        for (int j = j0 + threadIdx.x; j < j1; j += blockDim.x)
            sk[j - j0] = g_pre[j];
        __syncthreads();

        if (t < npre) {
            u64 mykey = g_pre[t];
            int len = j1 - j0;
            int cnt = 0, j = 0;
            for (; j + 4 <= len; j += 4) {
                cnt += (sk[j]     < mykey);
                cnt += (sk[j + 1] < mykey);
                cnt += (sk[j + 2] < mykey);
                cnt += (sk[j + 3] < mykey);
            }
            for (; j < len; ++j) cnt += (sk[j] < mykey);
            atomicAdd(&g_rank[t], cnt);
        }
    }

    // ---- ticket: last block to arrive runs finalize ----
    __syncthreads();
    if (threadIdx.x == 0) {
        __threadfence();
        unsigned v = atomicAdd(&g_done, 1u);
        amlast = (v == gridDim.x * gridDim.y - 1u);
    }
    __syncthreads();
    if (amlast) {
        for (int tt = threadIdx.x; tt < npre; tt += blockDim.x) {
            int rank = atomicExch(&g_rank[tt], 0);   // L2-coherent read + self-clean
            if (rank < nsamp) g_topidx[rank] = (uint32_t)g_pre[tt];
        }
        if (threadIdx.x == 0) g_done = 0u;
    }
}

// ---------------- K3: dense gather, MLP=4 (ring-buffer insert resolved on the fly) ----------------
__global__ void k_gather(const float* __restrict__ buf, const float* __restrict__ tr,
                         const int* __restrict__ d_ins, float* __restrict__ out,
                         int max_size, int data_len, int nsamp) {
    if (blockIdx.x == 0 && threadIdx.x == 0) g_npre = 0;  // deterministic reset

    const long p_ins = (long)(read_scalar(d_ins, DEF_INSERT) % max_size);
    const int nelem = nsamp * (FEAT / 4);   // 262144 float4s
    const int seg   = nelem >> 2;           // 65536
    int e = blockIdx.x * blockDim.x + threadIdx.x;
    if (e >= seg) return;
    int c = e & 63;

    const float4* src[4];
    int rows[4];
#pragma unroll
    for (int k = 0; k < 4; ++k) {
        int ee = e + k * seg;
        int row = ee >> 6;
        rows[k] = row;
        uint32_t idx = g_topidx[row];
        long off = (long)idx - p_ins;
        if (off < 0) off += max_size;
        src[k] = (off < (long)data_len)
            ? (const float4*)(tr + (size_t)off * FEAT)
            : (const float4*)(buf + (size_t)idx * FEAT);
    }
    float4 v0 = src[0][c];     // 4 independent loads in flight
    float4 v1 = src[1][c];
    float4 v2 = src[2][c];
    float4 v3 = src[3][c];
    ((float4*)(out + (size_t)rows[0] * FEAT))[c] = v0;
    ((float4*)(out + (size_t)rows[1] * FEAT))[c] = v1;
    ((float4*)(out + (size_t)rows[2] * FEAT))[c] = v2;
    ((float4*)(out + (size_t)rows[3] * FEAT))[c] = v3;
}

// ---------------- launcher ----------------
extern "C" void kernel_launch(void* const* d_in, const int* in_sizes, int n_in,
                              void* d_out, int out_size) {
    // Classify inputs by element count (robust to ordering):
    int i_buf = -1, i_tr = -1;
    int sc[3] = { -1, -1, -1 };
    int nsc = 0;
    for (int i = 0; i < n_in; ++i) {
        if (in_sizes[i] > 100000000)      i_buf = i;
        else if (in_sizes[i] > 1000000)   i_tr  = i;
        else if (in_sizes[i] >= 1 && in_sizes[i] <= 4 && nsc < 3) sc[nsc++] = i;
    }
    if (i_buf < 0) i_buf = 0;
    if (i_tr  < 0) i_tr  = 1;

    const float* buf   = (const float*)d_in[i_buf];
    const float* tr    = (const float*)d_in[i_tr];
    const int*   d_ins = (sc[0] >= 0) ? (const int*)d_in[sc[0]] : nullptr;
    const int*   d_sz  = (sc[1] >= 0) ? (const int*)d_in[sc[1]] : nullptr;

    int max_size = in_sizes[i_buf] / FEAT;   // 1,000,000
    int data_len = in_sizes[i_tr]  / FEAT;   // 16,384
    int nsamp    = out_size        / FEAT;   // 4,096

    k_hash_push<<<HB, 256>>>(d_sz, max_size, data_len, nsamp);
    dim3 rgrid(PRE_CAP / 256, JT);           // (64, 8)
    k_rank<<<rgrid, 256>>>(nsamp);
    int seg = (nsamp * (FEAT / 4)) / 4;      // 65536 threads, 4 float4 each
    k_gather<<<(seg + 255) / 256, 256>>>(buf, tr, d_ins, (float*)d_out,
                                         max_size, data_len, nsamp);
}

// round 9
// speedup vs baseline: 1.4811x; 1.4811x over previous
#include <cuda_runtime.h>
#include <cstdint>

#define FEAT      256
#define PRE_CAP   16384
#define JT        16
#define JCH       (PRE_CAP / JT)
#define DEF_INSERT 999000
#define HB        977                 // hash blocks
#define HT        (HB * 256)          // 250112 threads, 4 slots each

typedef unsigned long long u64;

// ---------------- device scratch (no allocations allowed; zero-init) ----------------
__device__ u64      g_pre[PRE_CAP];        // ((0x7FFFFF - r) << 32) | index
__device__ int      g_npre;                // reset in k_gather each run
__device__ int      g_rankp[JT][PRE_CAP];  // partial rank counts per j-tile
__device__ uint32_t g_topidx[PRE_CAP];     // ordered sampled indices

// ---------------- Threefry-2x32, 20 rounds, partitionable layout (JAX-exact) ----------------
__device__ __forceinline__ uint32_t rotl32(uint32_t x, int d) {
    return __funnelshift_l(x, x, d);
}

__device__ __forceinline__ uint32_t jax_bits32(uint32_t j) {
    const uint32_t k0 = 0u, k1 = 42u;
    const uint32_t ks2 = k0 ^ k1 ^ 0x1BD11BDAu;
    uint32_t x0 = 0u + k0, x1 = j + k1;
#define TF_R(r) { x0 += x1; x1 = rotl32(x1, (r)); x1 ^= x0; }
    TF_R(13) TF_R(15) TF_R(26) TF_R(6)   x0 += k1;  x1 += ks2 + 1u;
    TF_R(17) TF_R(29) TF_R(16) TF_R(24)  x0 += ks2; x1 += k0  + 2u;
    TF_R(13) TF_R(15) TF_R(26) TF_R(6)   x0 += k0;  x1 += k1  + 3u;
    TF_R(17) TF_R(29) TF_R(16) TF_R(24)  x0 += k1;  x1 += ks2 + 4u;
    TF_R(13) TF_R(15) TF_R(26) TF_R(6)   x0 += ks2; x1 += k0  + 5u;
#undef TF_R
    return x0 ^ x1;   // XOR-fold (jax_threefry_partitionable)
}

__device__ __forceinline__ int read_scalar(const int* p, int defv) {
    return p ? p[0] : defv;
}

__device__ __forceinline__ void warp_push(bool push, uint32_t r, int j, int lane) {
    unsigned mask = __ballot_sync(0xFFFFFFFFu, push);
    if (mask) {
        int leader = __ffs(mask) - 1;
        int base = 0;
        if (lane == leader) base = atomicAdd(&g_npre, __popc(mask));
        base = __shfl_sync(0xFFFFFFFFu, base, leader);
        if (push) {
            int pos = base + __popc(mask & ((1u << lane) - 1u));
            if (pos < PRE_CAP)
                g_pre[pos] = ((u64)(0x7FFFFFu - r) << 32) | (uint32_t)j;
        }
    }
}

// ---------------- K1: hash all slots, exactly 4 per thread, no loop ----------------
__global__ void __launch_bounds__(256)
k_hash_push(const int* __restrict__ d_size, int max_size, int data_len, int nsamp) {
    int new_size = read_scalar(d_size, max_size) + data_len;
    if (new_size > max_size) new_size = max_size;
    if (new_size < 0) new_size = 0;

    // keep top `keep` mantissa values so expected survivors ~= 1.25 * nsamp
    uint32_t precut = 0u;
    if (new_size > 0) {
        u64 keep = ((u64)nsamp * 5u / 4u) << 23;
        keep /= (u64)new_size;
        precut = (keep >= 0x800000ull) ? 0u : (uint32_t)(0x800000ull - keep);
    }

    const int lane = threadIdx.x & 31;
    const int j0 = blockIdx.x * 256 + threadIdx.x;
    const int j1 = j0 + HT, j2 = j0 + 2 * HT, j3 = j0 + 3 * HT;

    // four independent threefry chains -> 4x ILP on the ALU dep chain
    uint32_t r0 = 0u, r1 = 0u, r2 = 0u, r3 = 0u;
    bool p0 = false, p1 = false, p2 = false, p3 = false;
    if (j0 < new_size) { r0 = jax_bits32((uint32_t)j0) >> 9; p0 = (r0 >= precut); }
    if (j1 < new_size) { r1 = jax_bits32((uint32_t)j1) >> 9; p1 = (r1 >= precut); }
    if (j2 < new_size) { r2 = jax_bits32((uint32_t)j2) >> 9; p2 = (r2 >= precut); }
    if (j3 < new_size) { r3 = jax_bits32((uint32_t)j3) >> 9; p3 = (r3 >= precut); }
    warp_push(p0, r0, j0, lane);
    warp_push(p1, r1, j1, lane);
    warp_push(p2, r2, j2, lane);
    warp_push(p3, r3, j3, lane);
}

// ---------------- K2: tiled exact rank (partial counts, smem j-chunks) ----------------
__global__ void k_rank() {
    int npre = g_npre;
    if (npre > PRE_CAP) npre = PRE_CAP;
    if ((int)(blockIdx.x * blockDim.x) >= npre) return;   // uniform per block

    __shared__ u64 sk[JCH];
    int chunk = (npre + JT - 1) / JT;
    int j0 = blockIdx.y * chunk;
    int j1 = j0 + chunk; if (j1 > npre) j1 = npre;
    for (int j = j0 + threadIdx.x; j < j1; j += blockDim.x)
        sk[j - j0] = g_pre[j];
    __syncthreads();

    int t = blockIdx.x * blockDim.x + threadIdx.x;
    u64 mykey = (t < npre) ? g_pre[t] : ~0ull;
    int len = j1 - j0;
    int cnt = 0, j = 0;
    for (; j + 4 <= len; j += 4) {
        cnt += (sk[j]     < mykey);
        cnt += (sk[j + 1] < mykey);
        cnt += (sk[j + 2] < mykey);
        cnt += (sk[j + 3] < mykey);
    }
    for (; j < len; ++j) cnt += (sk[j] < mykey);
    if (t < npre) g_rankp[blockIdx.y][t] = cnt;
}

// ---------------- K3: finalize ranks -> ordered index list ----------------
__global__ void k_finalize(int nsamp) {
    int npre = g_npre;
    if (npre > PRE_CAP) npre = PRE_CAP;
    int t = blockIdx.x * blockDim.x + threadIdx.x;
    if (t >= npre) return;

    int rank = 0;
#pragma unroll
    for (int jt = 0; jt < JT; ++jt) rank += g_rankp[jt][t];   // coalesced in t
    if (rank < nsamp) g_topidx[rank] = (uint32_t)g_pre[t];
}

// ---------------- K4: dense gather, MLP=4 (ring-buffer insert resolved on the fly) ----------------
__global__ void k_gather(const float* __restrict__ buf, const float* __restrict__ tr,
                         const int* __restrict__ d_ins, float* __restrict__ out,
                         int max_size, int data_len, int nsamp) {
    if (blockIdx.x == 0 && threadIdx.x == 0) g_npre = 0;  // deterministic reset

    const long p_ins = (long)(read_scalar(d_ins, DEF_INSERT) % max_size);
    const int nelem = nsamp * (FEAT / 4);   // 262144 float4s
    const int seg   = nelem >> 2;           // 65536
    int e = blockIdx.x * blockDim.x + threadIdx.x;
    if (e >= seg) return;
    int c = e & 63;

    const float4* src[4];
    int rows[4];
#pragma unroll
    for (int k = 0; k < 4; ++k) {
        int ee = e + k * seg;
        int row = ee >> 6;
        rows[k] = row;
        uint32_t idx = g_topidx[row];
        long off = (long)idx - p_ins;
        if (off < 0) off += max_size;
        src[k] = (off < (long)data_len)
            ? (const float4*)(tr + (size_t)off * FEAT)
            : (const float4*)(buf + (size_t)idx * FEAT);
    }
    float4 v0 = src[0][c];     // 4 independent loads in flight
    float4 v1 = src[1][c];
    float4 v2 = src[2][c];
    float4 v3 = src[3][c];
    ((float4*)(out + (size_t)rows[0] * FEAT))[c] = v0;
    ((float4*)(out + (size_t)rows[1] * FEAT))[c] = v1;
    ((float4*)(out + (size_t)rows[2] * FEAT))[c] = v2;
    ((float4*)(out + (size_t)rows[3] * FEAT))[c] = v3;
}

// ---------------- launcher ----------------
extern "C" void kernel_launch(void* const* d_in, const int* in_sizes, int n_in,
                              void* d_out, int out_size) {
    // Classify inputs by element count (robust to ordering):
    int i_buf = -1, i_tr = -1;
    int sc[3] = { -1, -1, -1 };
    int nsc = 0;
    for (int i = 0; i < n_in; ++i) {
        if (in_sizes[i] > 100000000)      i_buf = i;
        else if (in_sizes[i] > 1000000)   i_tr  = i;
        else if (in_sizes[i] >= 1 && in_sizes[i] <= 4 && nsc < 3) sc[nsc++] = i;
    }
    if (i_buf < 0) i_buf = 0;
    if (i_tr  < 0) i_tr  = 1;

    const float* buf   = (const float*)d_in[i_buf];
    const float* tr    = (const float*)d_in[i_tr];
    const int*   d_ins = (sc[0] >= 0) ? (const int*)d_in[sc[0]] : nullptr;
    const int*   d_sz  = (sc[1] >= 0) ? (const int*)d_in[sc[1]] : nullptr;

    int max_size = in_sizes[i_buf] / FEAT;   // 1,000,000
    int data_len = in_sizes[i_tr]  / FEAT;   // 16,384
    int nsamp    = out_size        / FEAT;   // 4,096

    k_hash_push<<<HB, 256>>>(d_sz, max_size, data_len, nsamp);
    dim3 rgrid(PRE_CAP / 256, JT);           // (64, 16)
    k_rank<<<rgrid, 256>>>();
    k_finalize<<<PRE_CAP / 256, 256>>>(nsamp);
    int seg = (nsamp * (FEAT / 4)) / 4;      // 65536 threads, 4 float4 each
    k_gather<<<(seg + 255) / 256, 256>>>(buf, tr, d_ins, (float*)d_out,
                                         max_size, data_len, nsamp);
}

// round 11
// speedup vs baseline: 1.4981x; 1.0115x over previous
#include <cuda_runtime.h>
#include <cstdint>

#define FEAT      256
#define PRE_CAP   16384
#define JT        16
#define JCH       (PRE_CAP / JT)
#define DEF_INSERT 999000
#define HB        489                 // hash blocks
#define HT        (HB * 256)          // 125184 threads, 8 slots each (>= 1e6)

typedef unsigned long long u64;

// ---------------- device scratch (no allocations allowed; zero-init) ----------------
__device__ u64      g_pre[PRE_CAP];        // ((0x7FFFFF - r) << 32) | index
__device__ int      g_npre;                // K1 atomic counter; reset by K3 (never read there)
__device__ int      g_npre2;               // snapshot written by K2, read by K3
__device__ int      g_rankp[JT][PRE_CAP];  // partial rank counts per j-tile

// ---------------- Threefry-2x32, 20 rounds, partitionable layout (JAX-exact) ----------------
__device__ __forceinline__ uint32_t rotl32(uint32_t x, int d) {
    return __funnelshift_l(x, x, d);
}

__device__ __forceinline__ uint32_t jax_bits32(uint32_t j) {
    const uint32_t k0 = 0u, k1 = 42u;
    const uint32_t ks2 = k0 ^ k1 ^ 0x1BD11BDAu;
    uint32_t x0 = 0u + k0, x1 = j + k1;
#define TF_R(r) { x0 += x1; x1 = rotl32(x1, (r)); x1 ^= x0; }
    TF_R(13) TF_R(15) TF_R(26) TF_R(6)   x0 += k1;  x1 += ks2 + 1u;
    TF_R(17) TF_R(29) TF_R(16) TF_R(24)  x0 += ks2; x1 += k0  + 2u;
    TF_R(13) TF_R(15) TF_R(26) TF_R(6)   x0 += k0;  x1 += k1  + 3u;
    TF_R(17) TF_R(29) TF_R(16) TF_R(24)  x0 += k1;  x1 += ks2 + 4u;
    TF_R(13) TF_R(15) TF_R(26) TF_R(6)   x0 += ks2; x1 += k0  + 5u;
#undef TF_R
    return x0 ^ x1;   // XOR-fold (jax_threefry_partitionable)
}

__device__ __forceinline__ int read_scalar(const int* p, int defv) {
    return p ? p[0] : defv;
}

__device__ __forceinline__ void warp_push(bool push, uint32_t r, int j, int lane) {
    unsigned mask = __ballot_sync(0xFFFFFFFFu, push);
    if (mask) {
        int leader = __ffs(mask) - 1;
        int base = 0;
        if (lane == leader) base = atomicAdd(&g_npre, __popc(mask));
        base = __shfl_sync(0xFFFFFFFFu, base, leader);
        if (push) {
            int pos = base + __popc(mask & ((1u << lane) - 1u));
            if (pos < PRE_CAP)
                g_pre[pos] = ((u64)(0x7FFFFFu - r) << 32) | (uint32_t)j;
        }
    }
}

// ---------------- K1: hash all slots, exactly 8 per thread, no loop ----------------
__global__ void __launch_bounds__(256)
k_hash_push(const int* __restrict__ d_size, int max_size, int data_len, int nsamp) {
    int new_size = read_scalar(d_size, max_size) + data_len;
    if (new_size > max_size) new_size = max_size;
    if (new_size < 0) new_size = 0;

    // keep top ~1.25*nsamp expected survivors (float math: no u64 division)
    uint32_t precut = 0u;
    if (new_size > 0) {
        float keep_f = ((float)nsamp * 1.25f) * 8388608.0f / (float)new_size;
        u64 keep = (u64)keep_f;
        precut = (keep >= 0x800000ull) ? 0u : (uint32_t)(0x800000ull - keep);
    }

    const int lane = threadIdx.x & 31;
    const int base = blockIdx.x * 256 + threadIdx.x;

    uint32_t r[8];
    bool p[8];
#pragma unroll
    for (int k = 0; k < 8; ++k) { r[k] = 0u; p[k] = false; }
#pragma unroll
    for (int k = 0; k < 8; ++k) {          // 8 independent threefry chains
        int j = base + k * HT;
        if (j < new_size) {
            r[k] = jax_bits32((uint32_t)j) >> 9;
            p[k] = (r[k] >= precut);
        }
    }
#pragma unroll
    for (int k = 0; k < 8; ++k)
        warp_push(p[k], r[k], base + k * HT, lane);
}

// ---------------- K2: tiled exact rank + counter snapshot ----------------
__global__ void k_rank() {
    int npre = g_npre;
    if (npre > PRE_CAP) npre = PRE_CAP;

    // snapshot for K3 (written before any early return; one thread suffices,
    // K2->K3 stream ordering makes it visible)
    if (blockIdx.x == 0 && blockIdx.y == 0 && threadIdx.x == 0)
        g_npre2 = npre;

    if ((int)(blockIdx.x * blockDim.x) >= npre) return;   // uniform per block

    __shared__ u64 sk[JCH];
    int chunk = (npre + JT - 1) / JT;
    int j0 = blockIdx.y * chunk;
    int j1 = j0 + chunk; if (j1 > npre) j1 = npre;
    if (j0 >= npre) return;
    for (int j = j0 + threadIdx.x; j < j1; j += blockDim.x)
        sk[j - j0] = g_pre[j];
    __syncthreads();

    int t = blockIdx.x * blockDim.x + threadIdx.x;
    u64 mykey = (t < npre) ? g_pre[t] : ~0ull;
    int len = j1 - j0;
    int cnt = 0, j = 0;
    for (; j + 4 <= len; j += 4) {
        cnt += (sk[j]     < mykey);
        cnt += (sk[j + 1] < mykey);
        cnt += (sk[j + 2] < mykey);
        cnt += (sk[j + 3] < mykey);
    }
    for (; j < len; ++j) cnt += (sk[j] < mykey);
    if (t < npre) g_rankp[blockIdx.y][t] = cnt;
}

// ---------------- K3: fused finalize + gather, warp per candidate ----------------
__global__ void __launch_bounds__(256)
k_rank_gather(const float* __restrict__ buf, const float* __restrict__ tr,
              const int* __restrict__ d_ins, float* __restrict__ out,
              int max_size, int data_len, int nsamp) {
    // reset the K1 counter for the next run/replay; NO thread in this kernel
    // reads g_npre (only g_npre2), so this store races with nothing.
    if (blockIdx.x == 0 && threadIdx.x == 0) g_npre = 0;

    int npre = g_npre2;
    if (npre > PRE_CAP) npre = PRE_CAP;

    const int lane   = threadIdx.x & 31;
    const int warp   = (blockIdx.x * blockDim.x + threadIdx.x) >> 5;
    const int nwarps = (gridDim.x * blockDim.x) >> 5;
    const long p_ins = (long)(read_scalar(d_ins, DEF_INSERT) % max_size);

    for (int t = warp; t < npre; t += nwarps) {
        // lanes 0..15 fetch the 16 rank partials in parallel
        int part = (lane < JT) ? g_rankp[lane][t] : 0;
        int rank = __reduce_add_sync(0xFFFFFFFFu, part);
        if (rank >= nsamp) continue;

        uint32_t idx = (uint32_t)g_pre[t];          // broadcast load
        long off = (long)idx - p_ins;
        if (off < 0) off += max_size;
        const float4* src = (off < (long)data_len)
            ? (const float4*)(tr + (size_t)off * FEAT)
            : (const float4*)(buf + (size_t)idx * FEAT);
        float4* dst = (float4*)(out + (size_t)rank * FEAT);

        float4 v0 = src[lane];                      // two independent loads
        float4 v1 = src[lane + 32];
        dst[lane]      = v0;
        dst[lane + 32] = v1;
    }
}

// ---------------- launcher ----------------
extern "C" void kernel_launch(void* const* d_in, const int* in_sizes, int n_in,
                              void* d_out, int out_size) {
    // Classify inputs by element count (robust to ordering):
    int i_buf = -1, i_tr = -1;
    int sc[3] = { -1, -1, -1 };
    int nsc = 0;
    for (int i = 0; i < n_in; ++i) {
        if (in_sizes[i] > 100000000)      i_buf = i;
        else if (in_sizes[i] > 1000000)   i_tr  = i;
        else if (in_sizes[i] >= 1 && in_sizes[i] <= 4 && nsc < 3) sc[nsc++] = i;
    }
    if (i_buf < 0) i_buf = 0;
    if (i_tr  < 0) i_tr  = 1;

    const float* buf   = (const float*)d_in[i_buf];
    const float* tr    = (const float*)d_in[i_tr];
    const int*   d_ins = (sc[0] >= 0) ? (const int*)d_in[sc[0]] : nullptr;
    const int*   d_sz  = (sc[1] >= 0) ? (const int*)d_in[sc[1]] : nullptr;

    int max_size = in_sizes[i_buf] / FEAT;   // 1,000,000
    int data_len = in_sizes[i_tr]  / FEAT;   // 16,384
    int nsamp    = out_size        / FEAT;   // 4,096

    k_hash_push<<<HB, 256>>>(d_sz, max_size, data_len, nsamp);
    dim3 rgrid(PRE_CAP / 256, JT);           // (64, 16)
    k_rank<<<rgrid, 256>>>();
    k_rank_gather<<<768, 256>>>(buf, tr, d_ins, (float*)d_out,
                                max_size, data_len, nsamp);   // 6144 warps
}

// round 12
// speedup vs baseline: 1.7881x; 1.1936x over previous
#include <cuda_runtime.h>
#include <cstdint>

#define FEAT      256
#define PRE_CAP   16384
#define JT        16
#define JCH       (PRE_CAP / JT)
#define DEF_INSERT 999000
#define HB        1954                // hash blocks
#define HT        (HB * 256)          // 500224 threads, 2 slots each (>= 1e6)

typedef unsigned long long u64;

// ---------------- device scratch (no allocations allowed; zero-init) ----------------
__device__ u64      g_pre[PRE_CAP];        // ((0x7FFFFF - r) << 32) | index
__device__ int      g_npre;                // K1 atomic counter; reset by K3 (never read there)
__device__ int      g_npre2;               // snapshot written by K2, read by K3
__device__ int      g_rankp[JT][PRE_CAP];  // partial rank counts per j-tile

// ---------------- Threefry-2x32, 20 rounds, partitionable layout (JAX-exact) ----------------
__device__ __forceinline__ uint32_t rotl32(uint32_t x, int d) {
    return __funnelshift_l(x, x, d);
}

__device__ __forceinline__ uint32_t jax_bits32(uint32_t j) {
    const uint32_t k0 = 0u, k1 = 42u;
    const uint32_t ks2 = k0 ^ k1 ^ 0x1BD11BDAu;
    uint32_t x0 = 0u + k0, x1 = j + k1;
#define TF_R(r) { x0 += x1; x1 = rotl32(x1, (r)); x1 ^= x0; }
    TF_R(13) TF_R(15) TF_R(26) TF_R(6)   x0 += k1;  x1 += ks2 + 1u;
    TF_R(17) TF_R(29) TF_R(16) TF_R(24)  x0 += ks2; x1 += k0  + 2u;
    TF_R(13) TF_R(15) TF_R(26) TF_R(6)   x0 += k0;  x1 += k1  + 3u;
    TF_R(17) TF_R(29) TF_R(16) TF_R(24)  x0 += k1;  x1 += ks2 + 4u;
    TF_R(13) TF_R(15) TF_R(26) TF_R(6)   x0 += ks2; x1 += k0  + 5u;
#undef TF_R
    return x0 ^ x1;   // XOR-fold (jax_threefry_partitionable)
}

__device__ __forceinline__ int read_scalar(const int* p, int defv) {
    return p ? p[0] : defv;
}

__device__ __forceinline__ void warp_push(bool push, uint32_t r, int j, int lane) {
    unsigned mask = __ballot_sync(0xFFFFFFFFu, push);
    if (mask) {
        int leader = __ffs(mask) - 1;
        int base = 0;
        if (lane == leader) base = atomicAdd(&g_npre, __popc(mask));
        base = __shfl_sync(0xFFFFFFFFu, base, leader);
        if (push) {
            int pos = base + __popc(mask & ((1u << lane) - 1u));
            if (pos < PRE_CAP)
                g_pre[pos] = ((u64)(0x7FFFFFu - r) << 32) | (uint32_t)j;
        }
    }
}

// ---------------- K1: hash all slots, exactly 2 per thread, no loop, max occupancy ----------------
__global__ void __launch_bounds__(256)
k_hash_push(const int* __restrict__ d_size, int max_size, int data_len, int nsamp) {
    int new_size = read_scalar(d_size, max_size) + data_len;
    if (new_size > max_size) new_size = max_size;
    if (new_size < 0) new_size = 0;

    // keep top ~1.125*nsamp expected survivors (margin ~7.5 sigma)
    uint32_t precut = 0u;
    if (new_size > 0) {
        float keep_f = ((float)nsamp * 1.125f) * 8388608.0f / (float)new_size;
        u64 keep = (u64)keep_f;
        precut = (keep >= 0x800000ull) ? 0u : (uint32_t)(0x800000ull - keep);
    }

    const int lane = threadIdx.x & 31;
    const int j0 = blockIdx.x * 256 + threadIdx.x;
    const int j1 = j0 + HT;

    // two independent threefry chains
    uint32_t r0 = 0u, r1 = 0u;
    bool p0 = false, p1 = false;
    if (j0 < new_size) { r0 = jax_bits32((uint32_t)j0) >> 9; p0 = (r0 >= precut); }
    if (j1 < new_size) { r1 = jax_bits32((uint32_t)j1) >> 9; p1 = (r1 >= precut); }
    warp_push(p0, r0, j0, lane);
    warp_push(p1, r1, j1, lane);
}

// ---------------- K2: tiled exact rank + counter snapshot ----------------
__global__ void k_rank() {
    int npre = g_npre;
    if (npre > PRE_CAP) npre = PRE_CAP;

    // snapshot for K3 (one thread; K2->K3 stream ordering makes it visible)
    if (blockIdx.x == 0 && blockIdx.y == 0 && threadIdx.x == 0)
        g_npre2 = npre;

    if ((int)(blockIdx.x * blockDim.x) >= npre) return;   // uniform per block

    __shared__ u64 sk[JCH];
    int chunk = (npre + JT - 1) / JT;
    int j0 = blockIdx.y * chunk;
    int j1 = j0 + chunk; if (j1 > npre) j1 = npre;
    if (j0 >= npre) return;
    for (int j = j0 + threadIdx.x; j < j1; j += blockDim.x)
        sk[j - j0] = g_pre[j];
    __syncthreads();

    int t = blockIdx.x * blockDim.x + threadIdx.x;
    u64 mykey = (t < npre) ? g_pre[t] : ~0ull;
    int len = j1 - j0;
    int cnt = 0, j = 0;
    for (; j + 4 <= len; j += 4) {
        cnt += (sk[j]     < mykey);
        cnt += (sk[j + 1] < mykey);
        cnt += (sk[j + 2] < mykey);
        cnt += (sk[j + 3] < mykey);
    }
    for (; j < len; ++j) cnt += (sk[j] < mykey);
    if (t < npre) g_rankp[blockIdx.y][t] = cnt;
}

// ---------------- K3: fused finalize + gather, warp per candidate ----------------
__global__ void __launch_bounds__(256)
k_rank_gather(const float* __restrict__ buf, const float* __restrict__ tr,
              const int* __restrict__ d_ins, float* __restrict__ out,
              int max_size, int data_len, int nsamp) {
    // reset the K1 counter for the next run/replay; NO thread in this kernel
    // reads g_npre (only g_npre2), so this store races with nothing.
    if (blockIdx.x == 0 && threadIdx.x == 0) g_npre = 0;

    int npre = g_npre2;
    if (npre > PRE_CAP) npre = PRE_CAP;

    const int lane   = threadIdx.x & 31;
    const int warp   = (blockIdx.x * blockDim.x + threadIdx.x) >> 5;
    const int nwarps = (gridDim.x * blockDim.x) >> 5;
    const long p_ins = (long)(read_scalar(d_ins, DEF_INSERT) % max_size);

    for (int t = warp; t < npre; t += nwarps) {
        // lanes 0..15 fetch the 16 rank partials in parallel
        int part = (lane < JT) ? g_rankp[lane][t] : 0;
        int rank = __reduce_add_sync(0xFFFFFFFFu, part);
        if (rank >= nsamp) continue;

        uint32_t idx = (uint32_t)g_pre[t];          // broadcast load
        long off = (long)idx - p_ins;
        if (off < 0) off += max_size;
        const float4* src = (off < (long)data_len)
            ? (const float4*)(tr + (size_t)off * FEAT)
            : (const float4*)(buf + (size_t)idx * FEAT);
        float4* dst = (float4*)(out + (size_t)rank * FEAT);

        float4 v0 = src[lane];                      // two independent loads
        float4 v1 = src[lane + 32];
        dst[lane]      = v0;
        dst[lane + 32] = v1;
    }
}

// ---------------- launcher ----------------
extern "C" void kernel_launch(void* const* d_in, const int* in_sizes, int n_in,
                              void* d_out, int out_size) {
    // Classify inputs by element count (robust to ordering):
    int i_buf = -1, i_tr = -1;
    int sc[3] = { -1, -1, -1 };
    int nsc = 0;
    for (int i = 0; i < n_in; ++i) {
        if (in_sizes[i] > 100000000)      i_buf = i;
        else if (in_sizes[i] > 1000000)   i_tr  = i;
        else if (in_sizes[i] >= 1 && in_sizes[i] <= 4 && nsc < 3) sc[nsc++] = i;
    }
    if (i_buf < 0) i_buf = 0;
    if (i_tr  < 0) i_tr  = 1;

    const float* buf   = (const float*)d_in[i_buf];
    const float* tr    = (const float*)d_in[i_tr];
    const int*   d_ins = (sc[0] >= 0) ? (const int*)d_in[sc[0]] : nullptr;
    const int*   d_sz  = (sc[1] >= 0) ? (const int*)d_in[sc[1]] : nullptr;

    int max_size = in_sizes[i_buf] / FEAT;   // 1,000,000
    int data_len = in_sizes[i_tr]  / FEAT;   // 16,384
    int nsamp    = out_size        / FEAT;   // 4,096

    k_hash_push<<<HB, 256>>>(d_sz, max_size, data_len, nsamp);
    dim3 rgrid(PRE_CAP / 256, JT);           // (64, 16)
    k_rank<<<rgrid, 256>>>();
    k_rank_gather<<<768, 256>>>(buf, tr, d_ins, (float*)d_out,
                                max_size, data_len, nsamp);   // 6144 warps
}